// round 12
// baseline (speedup 1.0000x reference)
#include <cuda_runtime.h>

// TrajectoryGeneratorAR_goal: S=256 rollouts x N=64 agents, OBS=8 encoder LSTM
// steps, PRED=12 autoregressive decoder steps with pairwise pooling net.
// One CTA per rollout, 256 threads, smem-resident.
// Round 12 = R6 base (best: 1549us) + slack removal:
//  (1) uniform per-thread tile count (zero-weight pads) -> no ragged barrier
//  (2) barrier fusion: hjp reads only the quad's own h -> syncwarp, 5->4
//      __syncthreads per decoder step.

namespace {

constexpr int S_BATCH  = 256;
constexpr int NAG      = 64;
constexpr int BTOT     = S_BATCH * NAG;   // 16384
constexpr int OBS      = 8;
constexpr int PRED     = 12;
constexpr int H        = 16;
constexpr int NTHREADS = 256;
constexpr int MAXPAIRS = NAG * NAG;

struct __align__(16) Smem {
    float h[NAG][17];
    float c[NAG][17];
    float ctx[NAG][17];
    float hjp[NAG][65];
    float curr[NAG][2];
    float outp[NAG][2];
    float goal[NAG][2];
    unsigned long long nmask[NAG];
    int   pfx[NAG + 1];
    int   ntiles_u;                    // uniform tile count across CTA
    unsigned short plist[MAXPAIRS];    // (i<<6)|j, sorted by i
    alignas(16) float embW[32];
    alignas(16) float embB[16];
    alignas(16) float encWih[16*64];
    alignas(16) float encWhh[16*64];
    alignas(16) float encB[64];
    alignas(16) float decinW[18*16];
    alignas(16) float decinB[16];
    alignas(16) float decWih[16*64];
    alignas(16) float decWhh[16*64];
    alignas(16) float decB[64];
    alignas(16) float peW[32];
    alignas(16) float peB[16];
    alignas(16) float W1pT[64*16];   // [k][d]  (pool_W1 rows 0..15, transposed)
    alignas(16) float W1h [16*64];   // [d][k]  (pool_W1 rows 16..31)
    alignas(16) float b1  [64];
    alignas(16) float W2  [64*16];   // [k][u]
    alignas(16) float b2  [16];
    alignas(16) float h2p1W[18*16];
    alignas(16) float h2p1B[16];
    alignas(16) float h2p2W[16*4];
    alignas(16) float h2p2B[4];
};

__device__ __forceinline__ float sigm(float x)   { return 1.0f / (1.0f + __expf(-x)); }
__device__ __forceinline__ float tanh_f(float x) { return 2.0f / (1.0f + __expf(-2.0f * x)) - 1.0f; }

__device__ __forceinline__ void cpw(float* dst, const float* src, int n, int tid) {
    for (int k = tid; k < n; k += NTHREADS) dst[k] = src[k];
}

} // namespace

__global__ __launch_bounds__(NTHREADS)
void traj_ar_kernel(
    const float* __restrict__ traj_rel,
    const float* __restrict__ obs_pos,
    const float* __restrict__ goal_g,
    const float* __restrict__ embW, const float* __restrict__ embB,
    const float* __restrict__ encWih, const float* __restrict__ encWhh, const float* __restrict__ encB,
    const float* __restrict__ decinW, const float* __restrict__ decinB,
    const float* __restrict__ decWih, const float* __restrict__ decWhh, const float* __restrict__ decB,
    const float* __restrict__ peW, const float* __restrict__ peB,
    const float* __restrict__ W1, const float* __restrict__ b1,
    const float* __restrict__ W2, const float* __restrict__ b2,
    const float* __restrict__ h2p1W, const float* __restrict__ h2p1B,
    const float* __restrict__ h2p2W, const float* __restrict__ h2p2B,
    const int* __restrict__ nei,
    float* __restrict__ out, int out_size)
{
    extern __shared__ unsigned char smem_raw[];
    Smem& sm = *reinterpret_cast<Smem*>(smem_raw);
    const int tid = threadIdx.x;
    const int s   = blockIdx.x;

    if (s == 0 && tid == 0) {
        for (int idx = PRED * BTOT * 2; idx < out_size; ++idx) out[idx] = 0.0f;
    }

    // ---------------- weight staging + state init ----------------
    cpw(sm.embW,  embW,  32,  tid);  cpw(sm.embB,  embB,  16, tid);
    cpw(sm.encWih, encWih, 1024, tid); cpw(sm.encWhh, encWhh, 1024, tid); cpw(sm.encB, encB, 64, tid);
    cpw(sm.decinW, decinW, 288, tid);  cpw(sm.decinB, decinB, 16, tid);
    cpw(sm.decWih, decWih, 1024, tid); cpw(sm.decWhh, decWhh, 1024, tid); cpw(sm.decB, decB, 64, tid);
    cpw(sm.peW, peW, 32, tid); cpw(sm.peB, peB, 16, tid);
    for (int idx = tid; idx < 1024; idx += NTHREADS) {
        const int k = idx >> 4, d = idx & 15;
        sm.W1pT[idx] = W1[d * 64 + k];
    }
    cpw(sm.W1h, W1 + 1024, 1024, tid);
    cpw(sm.b1, b1, 64, tid); cpw(sm.W2, W2, 1024, tid); cpw(sm.b2, b2, 16, tid);
    cpw(sm.h2p1W, h2p1W, 288, tid); cpw(sm.h2p1B, h2p1B, 16, tid);
    cpw(sm.h2p2W, h2p2W, 64, tid);  cpw(sm.h2p2B, h2p2B, 4, tid);

    for (int idx = tid; idx < NAG * 17; idx += NTHREADS) {
        (&sm.h[0][0])[idx] = 0.0f; (&sm.c[0][0])[idx] = 0.0f; (&sm.ctx[0][0])[idx] = 0.0f;
    }
    if (tid < NAG) {
        sm.nmask[tid] = 0ull;
        const int b = s * NAG + tid;
        const float c0 = obs_pos[((OBS - 1) * BTOT + b) * 2 + 0];
        const float c1 = obs_pos[((OBS - 1) * BTOT + b) * 2 + 1];
        sm.curr[tid][0] = c0; sm.curr[tid][1] = c1;
        sm.outp[tid][0] = traj_rel[((OBS - 1) * BTOT + b) * 2 + 0];
        sm.outp[tid][1] = traj_rel[((OBS - 1) * BTOT + b) * 2 + 1];
        sm.goal[tid][0] = goal_g[b * 2 + 0] - c0;
        sm.goal[tid][1] = goal_g[b * 2 + 1] - c1;
    }
    __syncthreads();
    {
        const int base = s * (NAG * NAG);
        #pragma unroll
        for (int r = 0; r < (NAG * NAG) / NTHREADS; ++r) {
            const int flat = r * NTHREADS + tid;
            if (nei[base + flat] != 0)
                atomicOr(&sm.nmask[flat >> 6], 1ull << (flat & 63));
        }
    }
    __syncthreads();
    // ---- compacted (i,j) pair list, sorted by i (mask static over steps) ----
    if (tid == 0) {
        int run = 0;
        #pragma unroll
        for (int i = 0; i < NAG; ++i) { sm.pfx[i] = run; run += __popcll(sm.nmask[i]); }
        sm.pfx[NAG] = run;
        // uniform tile count: every thread runs ntiles_u tiles of 4 slots
        const int maxcnt = (run >> 8) + ((run & (NTHREADS - 1)) ? 1 : 0);
        sm.ntiles_u = (maxcnt + 3) >> 2;
    }
    __syncthreads();
    if (tid < NAG) {
        unsigned long long m = sm.nmask[tid];
        int w = sm.pfx[tid];
        const unsigned short ibase = (unsigned short)(tid << 6);
        while (m) {
            const int j = __ffsll((long long)m) - 1;
            m &= m - 1;
            sm.plist[w++] = (unsigned short)(ibase | j);
        }
    }
    __syncthreads();
    const int P       = sm.pfx[NAG];
    const int pbase   = P >> 8;
    const int prem    = P & (NTHREADS - 1);
    const int mystart = tid * pbase + (tid < prem ? tid : prem);
    const int mycnt   = pbase + (tid < prem ? 1 : 0);
    const int ntiles  = sm.ntiles_u;

    const int a   = tid >> 2;
    const int sub = tid & 3;

    // ---------------- history encoder ----------------
    for (int t = 0; t < OBS; ++t) {
        const int b = s * NAG + a;
        const float x0 = traj_rel[(t * BTOT + b) * 2 + 0];
        const float x1 = traj_rel[(t * BTOT + b) * 2 + 1];
        float emb[H];
        #pragma unroll
        for (int u = 0; u < H; ++u)
            emb[u] = fmaxf(fmaf(x0, sm.embW[u], fmaf(x1, sm.embW[16 + u], sm.embB[u])), 0.0f);
        float hold[H];
        #pragma unroll
        for (int d = 0; d < H; ++d) hold[d] = sm.h[a][d];
        float hn[4], cn[4];
        #pragma unroll
        for (int q = 0; q < 4; ++q) {
            const int u = sub * 4 + q;
            float gi = sm.encB[u], gf = sm.encB[16 + u], gg = sm.encB[32 + u], go = sm.encB[48 + u];
            #pragma unroll
            for (int d = 0; d < H; ++d) {
                const float e = emb[d], hd = hold[d];
                gi = fmaf(e, sm.encWih[d * 64 + u],        gi); gi = fmaf(hd, sm.encWhh[d * 64 + u],        gi);
                gf = fmaf(e, sm.encWih[d * 64 + 16 + u],   gf); gf = fmaf(hd, sm.encWhh[d * 64 + 16 + u],   gf);
                gg = fmaf(e, sm.encWih[d * 64 + 32 + u],   gg); gg = fmaf(hd, sm.encWhh[d * 64 + 32 + u],   gg);
                go = fmaf(e, sm.encWih[d * 64 + 48 + u],   go); go = fmaf(hd, sm.encWhh[d * 64 + 48 + u],   go);
            }
            const float cN = sigm(gf) * sm.c[a][u] + sigm(gi) * tanh_f(gg);
            cn[q] = cN; hn[q] = sigm(go) * tanh_f(cN);
        }
        __syncwarp();
        #pragma unroll
        for (int q = 0; q < 4; ++q) { sm.h[a][sub * 4 + q] = hn[q]; sm.c[a][sub * 4 + q] = cn[q]; }
        __syncwarp();
    }
    #pragma unroll
    for (int q = 0; q < 4; ++q) sm.c[a][sub * 4 + q] = 0.0f;
    __syncthreads();

    // ---------------- autoregressive decoder ----------------
    for (int step = 0; step < PRED; ++step) {
        // --- decoder input embed + LSTM (quad per agent) ---
        float ctxv[H];
        #pragma unroll
        for (int d = 0; d < H; ++d) ctxv[d] = sm.ctx[a][d];
        const float o0 = sm.outp[a][0], o1 = sm.outp[a][1];
        float emb[H];
        #pragma unroll
        for (int u = 0; u < H; ++u) {
            float acc = sm.decinB[u];
            #pragma unroll
            for (int d = 0; d < H; ++d) acc = fmaf(ctxv[d], sm.decinW[d * 16 + u], acc);
            acc = fmaf(o0, sm.decinW[256 + u], fmaf(o1, sm.decinW[272 + u], acc));
            emb[u] = fmaxf(acc, 0.0f);
        }
        float hold[H];
        #pragma unroll
        for (int d = 0; d < H; ++d) hold[d] = sm.h[a][d];
        float hn[4], cn[4];
        #pragma unroll
        for (int q = 0; q < 4; ++q) {
            const int u = sub * 4 + q;
            float gi = sm.decB[u], gf = sm.decB[16 + u], gg = sm.decB[32 + u], go = sm.decB[48 + u];
            #pragma unroll
            for (int d = 0; d < H; ++d) {
                const float e = emb[d], hd = hold[d];
                gi = fmaf(e, sm.decWih[d * 64 + u],        gi); gi = fmaf(hd, sm.decWhh[d * 64 + u],        gi);
                gf = fmaf(e, sm.decWih[d * 64 + 16 + u],   gf); gf = fmaf(hd, sm.decWhh[d * 64 + 16 + u],   gf);
                gg = fmaf(e, sm.decWih[d * 64 + 32 + u],   gg); gg = fmaf(hd, sm.decWhh[d * 64 + 32 + u],   gg);
                go = fmaf(e, sm.decWih[d * 64 + 48 + u],   go); go = fmaf(hd, sm.decWhh[d * 64 + 48 + u],   go);
            }
            const float cN = sigm(gf) * sm.c[a][u] + sigm(gi) * tanh_f(gg);
            cn[q] = cN; hn[q] = sigm(go) * tanh_f(cN);
        }
        __syncthreads();   // all reads of old h complete (CTA-wide)
        #pragma unroll
        for (int q = 0; q < 4; ++q) { sm.h[a][sub * 4 + q] = hn[q]; sm.c[a][sub * 4 + q] = cn[q]; }
        __syncwarp();      // quad's h[a] complete (intra-warp) -> hjp can start

        // --- hjp[j=a][k] = h_a . W1h[:,k] + b1[k]  (fused: needs only quad's h) ---
        {
            const int j = a, k0 = sub * 16;
            float hv[H];
            #pragma unroll
            for (int d = 0; d < H; ++d) hv[d] = sm.h[j][d];
            #pragma unroll
            for (int kk = 0; kk < 16; ++kk) {
                const int k = k0 + kk;
                float acc = sm.b1[k];
                #pragma unroll
                for (int d = 0; d < H; ++d) acc = fmaf(hv[d], sm.W1h[d * 64 + k], acc);
                sm.hjp[j][k] = acc;
            }
        }
        for (int idx = tid; idx < NAG * 17; idx += NTHREADS) (&sm.ctx[0][0])[idx] = 0.0f;
        __syncthreads();   // hjp + ctx-zero visible CTA-wide

        // ---- pooling: uniform ntiles tiles of 4 pairs (zero-weight pads) ----
        {
            int   cur_i = -1;
            float acc[H];
            for (int tile = 0; tile < ntiles; ++tile) {
                const int t = tile * 4;
                int pi[4], pj[4];
                float pw[4];
                #pragma unroll
                for (int e = 0; e < 4; ++e) {
                    const int tt  = t + e;
                    const bool real = (tt < mycnt);
                    const int idx = mystart + (real ? tt : (mycnt > 0 ? mycnt - 1 : 0));
                    const int pr  = sm.plist[idx];
                    pi[e] = pr >> 6; pj[e] = pr & 63;
                    pw[e] = real ? 1.0f : 0.0f;
                }
                float pe[4][H], m[4][H];
                #pragma unroll
                for (int e = 0; e < 4; ++e) {
                    const float dx = sm.curr[pi[e]][0] - sm.curr[pj[e]][0];
                    const float dy = sm.curr[pi[e]][1] - sm.curr[pj[e]][1];
                    #pragma unroll
                    for (int u = 0; u < H; ++u) {
                        pe[e][u] = fmaxf(fmaf(dx, sm.peW[u], fmaf(dy, sm.peW[16 + u], sm.peB[u])), 0.0f);
                        m[e][u]  = 0.0f;
                    }
                }
                const float* __restrict__ hj0 = sm.hjp[pj[0]];
                const float* __restrict__ hj1 = sm.hjp[pj[1]];
                const float* __restrict__ hj2 = sm.hjp[pj[2]];
                const float* __restrict__ hj3 = sm.hjp[pj[3]];
                for (int k = 0; k < 64; ++k) {
                    const float4* w1p4 = reinterpret_cast<const float4*>(sm.W1pT + (k << 4));
                    const float4 wA = w1p4[0], wB = w1p4[1], wC = w1p4[2], wD = w1p4[3];
                    const float w1[H] = { wA.x, wA.y, wA.z, wA.w, wB.x, wB.y, wB.z, wB.w,
                                          wC.x, wC.y, wC.z, wC.w, wD.x, wD.y, wD.z, wD.w };
                    float a0 = hj0[k];
                    float a1 = hj1[k];
                    float a2 = hj2[k];
                    float a3 = hj3[k];
                    #pragma unroll
                    for (int d = 0; d < H; ++d) {
                        a0 = fmaf(pe[0][d], w1[d], a0);
                        a1 = fmaf(pe[1][d], w1[d], a1);
                        a2 = fmaf(pe[2][d], w1[d], a2);
                        a3 = fmaf(pe[3][d], w1[d], a3);
                    }
                    a0 = fmaxf(a0, 0.0f); a1 = fmaxf(a1, 0.0f);
                    a2 = fmaxf(a2, 0.0f); a3 = fmaxf(a3, 0.0f);
                    const float4* w2p4 = reinterpret_cast<const float4*>(sm.W2 + (k << 4));
                    const float4 vA = w2p4[0], vB = w2p4[1], vC = w2p4[2], vD = w2p4[3];
                    const float w2[H] = { vA.x, vA.y, vA.z, vA.w, vB.x, vB.y, vB.z, vB.w,
                                          vC.x, vC.y, vC.z, vC.w, vD.x, vD.y, vD.z, vD.w };
                    #pragma unroll
                    for (int u = 0; u < H; ++u) {
                        m[0][u] = fmaf(a0, w2[u], m[0][u]);
                        m[1][u] = fmaf(a1, w2[u], m[1][u]);
                        m[2][u] = fmaf(a2, w2[u], m[2][u]);
                        m[3][u] = fmaf(a3, w2[u], m[3][u]);
                    }
                }
                // epilogue: segment accumulation over i (list i-sorted; pads keep cur_i)
                #pragma unroll
                for (int e = 0; e < 4; ++e) {
                    if (pi[e] == cur_i) {
                        #pragma unroll
                        for (int u = 0; u < H; ++u)
                            acc[u] = fmaf(pw[e], fmaxf(m[e][u] + sm.b2[u], 0.0f), acc[u]);
                    } else {
                        if (cur_i >= 0) {
                            #pragma unroll
                            for (int u = 0; u < H; ++u) atomicAdd(&sm.ctx[cur_i][u], acc[u]);
                        }
                        cur_i = pi[e];
                        #pragma unroll
                        for (int u = 0; u < H; ++u)
                            acc[u] = pw[e] * fmaxf(m[e][u] + sm.b2[u], 0.0f);
                    }
                }
            }
            if (cur_i >= 0 && mycnt > 0) {
                #pragma unroll
                for (int u = 0; u < H; ++u) atomicAdd(&sm.ctx[cur_i][u], acc[u]);
            }
        }
        __syncthreads();

        // --- output head (one thread per agent) ---
        if (tid < NAG) {
            float hv[H], hh[H];
            #pragma unroll
            for (int u = 0; u < H; ++u) hv[u] = sm.h[tid][u] + sm.ctx[tid][u];
            const float g0 = sm.goal[tid][0], g1 = sm.goal[tid][1];
            #pragma unroll
            for (int u = 0; u < H; ++u) {
                float acc = sm.h2p1B[u];
                #pragma unroll
                for (int d = 0; d < H; ++d) acc = fmaf(hv[d], sm.h2p1W[d * 16 + u], acc);
                acc = fmaf(g0, sm.h2p1W[256 + u], fmaf(g1, sm.h2p1W[272 + u], acc));
                hh[u] = fmaxf(acc, 0.0f);
            }
            float mu0 = sm.h2p2B[0], mu1 = sm.h2p2B[1];
            #pragma unroll
            for (int d = 0; d < H; ++d) {
                mu0 = fmaf(hh[d], sm.h2p2W[d * 4 + 0], mu0);
                mu1 = fmaf(hh[d], sm.h2p2W[d * 4 + 1], mu1);
            }
            const int b = s * NAG + tid;
            out[(step * BTOT + b) * 2 + 0] = mu0;
            out[(step * BTOT + b) * 2 + 1] = mu1;
            sm.outp[tid][0] = mu0; sm.outp[tid][1] = mu1;
            sm.curr[tid][0] += mu0; sm.curr[tid][1] += mu1;
        }
        __syncthreads();
    }
}

extern "C" void kernel_launch(void* const* d_in, const int* in_sizes, int n_in,
                              void* d_out, int out_size)
{
    (void)in_sizes; (void)n_in;
    cudaFuncSetAttribute(traj_ar_kernel, cudaFuncAttributeMaxDynamicSharedMemorySize,
                         (int)sizeof(Smem));
    traj_ar_kernel<<<S_BATCH, NTHREADS, sizeof(Smem)>>>(
        (const float*)d_in[0],
        (const float*)d_in[1],
        (const float*)d_in[2],
        (const float*)d_in[4],  (const float*)d_in[5],
        (const float*)d_in[6],  (const float*)d_in[7],  (const float*)d_in[8],
        (const float*)d_in[9],  (const float*)d_in[10],
        (const float*)d_in[11], (const float*)d_in[12], (const float*)d_in[13],
        (const float*)d_in[14], (const float*)d_in[15],
        (const float*)d_in[16], (const float*)d_in[17],
        (const float*)d_in[18], (const float*)d_in[19],
        (const float*)d_in[20], (const float*)d_in[21],
        (const float*)d_in[22], (const float*)d_in[23],
        (const int*)d_in[24],
        (float*)d_out, out_size);
}

// round 13
// speedup vs baseline: 1.0937x; 1.0937x over previous
#include <cuda_runtime.h>

// TrajectoryGeneratorAR_goal: S=256 rollouts x N=64 agents, OBS=8 encoder LSTM
// steps, PRED=12 autoregressive decoder steps with pairwise pooling net.
// One CTA per rollout, 256 threads, smem-resident.
// Round 13 = R6 (best clean base: 1549us, per-thread tile counts) + the one
// R12 change that measurably helped (issue 44.5->48.9%): barrier fusion.
// After the LSTM h-write only a __syncwarp (hjp needs just the quad's own
// h[a]); hjp + ctx-zero fold into that phase -> 4 CTA barriers/step, not 5.
// R12's uniform-tile padding (a ~17% work bomb) is reverted.

namespace {

constexpr int S_BATCH  = 256;
constexpr int NAG      = 64;
constexpr int BTOT     = S_BATCH * NAG;   // 16384
constexpr int OBS      = 8;
constexpr int PRED     = 12;
constexpr int H        = 16;
constexpr int NTHREADS = 256;
constexpr int MAXPAIRS = NAG * NAG;

struct __align__(16) Smem {
    float h[NAG][17];
    float c[NAG][17];
    float ctx[NAG][17];
    float hjp[NAG][65];
    float curr[NAG][2];
    float outp[NAG][2];
    float goal[NAG][2];
    unsigned long long nmask[NAG];
    int   pfx[NAG + 1];
    unsigned short plist[MAXPAIRS];    // (i<<6)|j, sorted by i
    alignas(16) float embW[32];
    alignas(16) float embB[16];
    alignas(16) float encWih[16*64];
    alignas(16) float encWhh[16*64];
    alignas(16) float encB[64];
    alignas(16) float decinW[18*16];
    alignas(16) float decinB[16];
    alignas(16) float decWih[16*64];
    alignas(16) float decWhh[16*64];
    alignas(16) float decB[64];
    alignas(16) float peW[32];
    alignas(16) float peB[16];
    alignas(16) float W1pT[64*16];   // [k][d]  (pool_W1 rows 0..15, transposed)
    alignas(16) float W1h [16*64];   // [d][k]  (pool_W1 rows 16..31)
    alignas(16) float b1  [64];
    alignas(16) float W2  [64*16];   // [k][u]
    alignas(16) float b2  [16];
    alignas(16) float h2p1W[18*16];
    alignas(16) float h2p1B[16];
    alignas(16) float h2p2W[16*4];
    alignas(16) float h2p2B[4];
};

__device__ __forceinline__ float sigm(float x)   { return 1.0f / (1.0f + __expf(-x)); }
__device__ __forceinline__ float tanh_f(float x) { return 2.0f / (1.0f + __expf(-2.0f * x)) - 1.0f; }

__device__ __forceinline__ void cpw(float* dst, const float* src, int n, int tid) {
    for (int k = tid; k < n; k += NTHREADS) dst[k] = src[k];
}

} // namespace

__global__ __launch_bounds__(NTHREADS)
void traj_ar_kernel(
    const float* __restrict__ traj_rel,
    const float* __restrict__ obs_pos,
    const float* __restrict__ goal_g,
    const float* __restrict__ embW, const float* __restrict__ embB,
    const float* __restrict__ encWih, const float* __restrict__ encWhh, const float* __restrict__ encB,
    const float* __restrict__ decinW, const float* __restrict__ decinB,
    const float* __restrict__ decWih, const float* __restrict__ decWhh, const float* __restrict__ decB,
    const float* __restrict__ peW, const float* __restrict__ peB,
    const float* __restrict__ W1, const float* __restrict__ b1,
    const float* __restrict__ W2, const float* __restrict__ b2,
    const float* __restrict__ h2p1W, const float* __restrict__ h2p1B,
    const float* __restrict__ h2p2W, const float* __restrict__ h2p2B,
    const int* __restrict__ nei,
    float* __restrict__ out, int out_size)
{
    extern __shared__ unsigned char smem_raw[];
    Smem& sm = *reinterpret_cast<Smem*>(smem_raw);
    const int tid = threadIdx.x;
    const int s   = blockIdx.x;

    if (s == 0 && tid == 0) {
        for (int idx = PRED * BTOT * 2; idx < out_size; ++idx) out[idx] = 0.0f;
    }

    // ---------------- weight staging + state init ----------------
    cpw(sm.embW,  embW,  32,  tid);  cpw(sm.embB,  embB,  16, tid);
    cpw(sm.encWih, encWih, 1024, tid); cpw(sm.encWhh, encWhh, 1024, tid); cpw(sm.encB, encB, 64, tid);
    cpw(sm.decinW, decinW, 288, tid);  cpw(sm.decinB, decinB, 16, tid);
    cpw(sm.decWih, decWih, 1024, tid); cpw(sm.decWhh, decWhh, 1024, tid); cpw(sm.decB, decB, 64, tid);
    cpw(sm.peW, peW, 32, tid); cpw(sm.peB, peB, 16, tid);
    for (int idx = tid; idx < 1024; idx += NTHREADS) {
        const int k = idx >> 4, d = idx & 15;
        sm.W1pT[idx] = W1[d * 64 + k];
    }
    cpw(sm.W1h, W1 + 1024, 1024, tid);
    cpw(sm.b1, b1, 64, tid); cpw(sm.W2, W2, 1024, tid); cpw(sm.b2, b2, 16, tid);
    cpw(sm.h2p1W, h2p1W, 288, tid); cpw(sm.h2p1B, h2p1B, 16, tid);
    cpw(sm.h2p2W, h2p2W, 64, tid);  cpw(sm.h2p2B, h2p2B, 4, tid);

    for (int idx = tid; idx < NAG * 17; idx += NTHREADS) {
        (&sm.h[0][0])[idx] = 0.0f; (&sm.c[0][0])[idx] = 0.0f; (&sm.ctx[0][0])[idx] = 0.0f;
    }
    if (tid < NAG) {
        sm.nmask[tid] = 0ull;
        const int b = s * NAG + tid;
        const float c0 = obs_pos[((OBS - 1) * BTOT + b) * 2 + 0];
        const float c1 = obs_pos[((OBS - 1) * BTOT + b) * 2 + 1];
        sm.curr[tid][0] = c0; sm.curr[tid][1] = c1;
        sm.outp[tid][0] = traj_rel[((OBS - 1) * BTOT + b) * 2 + 0];
        sm.outp[tid][1] = traj_rel[((OBS - 1) * BTOT + b) * 2 + 1];
        sm.goal[tid][0] = goal_g[b * 2 + 0] - c0;
        sm.goal[tid][1] = goal_g[b * 2 + 1] - c1;
    }
    __syncthreads();
    {
        const int base = s * (NAG * NAG);
        #pragma unroll
        for (int r = 0; r < (NAG * NAG) / NTHREADS; ++r) {
            const int flat = r * NTHREADS + tid;
            if (nei[base + flat] != 0)
                atomicOr(&sm.nmask[flat >> 6], 1ull << (flat & 63));
        }
    }
    __syncthreads();
    // ---- compacted (i,j) pair list, sorted by i (mask static over steps) ----
    if (tid == 0) {
        int run = 0;
        #pragma unroll
        for (int i = 0; i < NAG; ++i) { sm.pfx[i] = run; run += __popcll(sm.nmask[i]); }
        sm.pfx[NAG] = run;
    }
    __syncthreads();
    if (tid < NAG) {
        unsigned long long m = sm.nmask[tid];
        int w = sm.pfx[tid];
        const unsigned short ibase = (unsigned short)(tid << 6);
        while (m) {
            const int j = __ffsll((long long)m) - 1;
            m &= m - 1;
            sm.plist[w++] = (unsigned short)(ibase | j);
        }
    }
    __syncthreads();
    const int P       = sm.pfx[NAG];
    const int pbase   = P >> 8;
    const int prem    = P & (NTHREADS - 1);
    const int mystart = tid * pbase + (tid < prem ? tid : prem);
    const int mycnt   = pbase + (tid < prem ? 1 : 0);

    const int a   = tid >> 2;
    const int sub = tid & 3;

    // ---------------- history encoder ----------------
    for (int t = 0; t < OBS; ++t) {
        const int b = s * NAG + a;
        const float x0 = traj_rel[(t * BTOT + b) * 2 + 0];
        const float x1 = traj_rel[(t * BTOT + b) * 2 + 1];
        float emb[H];
        #pragma unroll
        for (int u = 0; u < H; ++u)
            emb[u] = fmaxf(fmaf(x0, sm.embW[u], fmaf(x1, sm.embW[16 + u], sm.embB[u])), 0.0f);
        float hold[H];
        #pragma unroll
        for (int d = 0; d < H; ++d) hold[d] = sm.h[a][d];
        float hn[4], cn[4];
        #pragma unroll
        for (int q = 0; q < 4; ++q) {
            const int u = sub * 4 + q;
            float gi = sm.encB[u], gf = sm.encB[16 + u], gg = sm.encB[32 + u], go = sm.encB[48 + u];
            #pragma unroll
            for (int d = 0; d < H; ++d) {
                const float e = emb[d], hd = hold[d];
                gi = fmaf(e, sm.encWih[d * 64 + u],        gi); gi = fmaf(hd, sm.encWhh[d * 64 + u],        gi);
                gf = fmaf(e, sm.encWih[d * 64 + 16 + u],   gf); gf = fmaf(hd, sm.encWhh[d * 64 + 16 + u],   gf);
                gg = fmaf(e, sm.encWih[d * 64 + 32 + u],   gg); gg = fmaf(hd, sm.encWhh[d * 64 + 32 + u],   gg);
                go = fmaf(e, sm.encWih[d * 64 + 48 + u],   go); go = fmaf(hd, sm.encWhh[d * 64 + 48 + u],   go);
            }
            const float cN = sigm(gf) * sm.c[a][u] + sigm(gi) * tanh_f(gg);
            cn[q] = cN; hn[q] = sigm(go) * tanh_f(cN);
        }
        __syncwarp();
        #pragma unroll
        for (int q = 0; q < 4; ++q) { sm.h[a][sub * 4 + q] = hn[q]; sm.c[a][sub * 4 + q] = cn[q]; }
        __syncwarp();
    }
    #pragma unroll
    for (int q = 0; q < 4; ++q) sm.c[a][sub * 4 + q] = 0.0f;
    __syncthreads();

    // ---------------- autoregressive decoder ----------------
    for (int step = 0; step < PRED; ++step) {
        // --- decoder input embed + LSTM (quad per agent) ---
        float ctxv[H];
        #pragma unroll
        for (int d = 0; d < H; ++d) ctxv[d] = sm.ctx[a][d];
        const float o0 = sm.outp[a][0], o1 = sm.outp[a][1];
        float emb[H];
        #pragma unroll
        for (int u = 0; u < H; ++u) {
            float acc = sm.decinB[u];
            #pragma unroll
            for (int d = 0; d < H; ++d) acc = fmaf(ctxv[d], sm.decinW[d * 16 + u], acc);
            acc = fmaf(o0, sm.decinW[256 + u], fmaf(o1, sm.decinW[272 + u], acc));
            emb[u] = fmaxf(acc, 0.0f);
        }
        float hold[H];
        #pragma unroll
        for (int d = 0; d < H; ++d) hold[d] = sm.h[a][d];
        float hn[4], cn[4];
        #pragma unroll
        for (int q = 0; q < 4; ++q) {
            const int u = sub * 4 + q;
            float gi = sm.decB[u], gf = sm.decB[16 + u], gg = sm.decB[32 + u], go = sm.decB[48 + u];
            #pragma unroll
            for (int d = 0; d < H; ++d) {
                const float e = emb[d], hd = hold[d];
                gi = fmaf(e, sm.decWih[d * 64 + u],        gi); gi = fmaf(hd, sm.decWhh[d * 64 + u],        gi);
                gf = fmaf(e, sm.decWih[d * 64 + 16 + u],   gf); gf = fmaf(hd, sm.decWhh[d * 64 + 16 + u],   gf);
                gg = fmaf(e, sm.decWih[d * 64 + 32 + u],   gg); gg = fmaf(hd, sm.decWhh[d * 64 + 32 + u],   gg);
                go = fmaf(e, sm.decWih[d * 64 + 48 + u],   go); go = fmaf(hd, sm.decWhh[d * 64 + 48 + u],   go);
            }
            const float cN = sigm(gf) * sm.c[a][u] + sigm(gi) * tanh_f(gg);
            cn[q] = cN; hn[q] = sigm(go) * tanh_f(cN);
        }
        __syncthreads();   // B1: all reads of old h/ctx complete (CTA-wide)
        #pragma unroll
        for (int q = 0; q < 4; ++q) { sm.h[a][sub * 4 + q] = hn[q]; sm.c[a][sub * 4 + q] = cn[q]; }
        __syncwarp();      // quad's h[a] visible intra-warp -> hjp can start now

        // --- hjp[j=a][k] = h_a . W1h[:,k] + b1[k]  (needs only quad's own h) ---
        {
            const int j = a, k0 = sub * 16;
            float hv[H];
            #pragma unroll
            for (int d = 0; d < H; ++d) hv[d] = sm.h[j][d];
            #pragma unroll
            for (int kk = 0; kk < 16; ++kk) {
                const int k = k0 + kk;
                float acc = sm.b1[k];
                #pragma unroll
                for (int d = 0; d < H; ++d) acc = fmaf(hv[d], sm.W1h[d * 64 + k], acc);
                sm.hjp[j][k] = acc;
            }
        }
        for (int idx = tid; idx < NAG * 17; idx += NTHREADS) (&sm.ctx[0][0])[idx] = 0.0f;
        __syncthreads();   // B2: hjp + ctx-zero + h visible CTA-wide

        // ---- pooling: tiles of 4 pairs, per-thread count (R6 tail handling) ----
        if (mycnt > 0) {
            int   cur_i = -1;
            float acc[H];
            for (int t = 0; t < mycnt; t += 4) {
                int pi[4], pj[4];
                float pw[4];
                #pragma unroll
                for (int e = 0; e < 4; ++e) {
                    const int tt  = t + e;
                    const int idx = mystart + (tt < mycnt ? tt : mycnt - 1);
                    const int pr  = sm.plist[idx];
                    pi[e] = pr >> 6; pj[e] = pr & 63;
                    pw[e] = (tt < mycnt) ? 1.0f : 0.0f;
                }
                float pe[4][H], m[4][H];
                #pragma unroll
                for (int e = 0; e < 4; ++e) {
                    const float dx = sm.curr[pi[e]][0] - sm.curr[pj[e]][0];
                    const float dy = sm.curr[pi[e]][1] - sm.curr[pj[e]][1];
                    #pragma unroll
                    for (int u = 0; u < H; ++u) {
                        pe[e][u] = fmaxf(fmaf(dx, sm.peW[u], fmaf(dy, sm.peW[16 + u], sm.peB[u])), 0.0f);
                        m[e][u]  = 0.0f;
                    }
                }
                const float* __restrict__ hj0 = sm.hjp[pj[0]];
                const float* __restrict__ hj1 = sm.hjp[pj[1]];
                const float* __restrict__ hj2 = sm.hjp[pj[2]];
                const float* __restrict__ hj3 = sm.hjp[pj[3]];
                for (int k = 0; k < 64; ++k) {
                    const float4* w1p4 = reinterpret_cast<const float4*>(sm.W1pT + (k << 4));
                    const float4 wA = w1p4[0], wB = w1p4[1], wC = w1p4[2], wD = w1p4[3];
                    const float w1[H] = { wA.x, wA.y, wA.z, wA.w, wB.x, wB.y, wB.z, wB.w,
                                          wC.x, wC.y, wC.z, wC.w, wD.x, wD.y, wD.z, wD.w };
                    float a0 = hj0[k];
                    float a1 = hj1[k];
                    float a2 = hj2[k];
                    float a3 = hj3[k];
                    #pragma unroll
                    for (int d = 0; d < H; ++d) {
                        a0 = fmaf(pe[0][d], w1[d], a0);
                        a1 = fmaf(pe[1][d], w1[d], a1);
                        a2 = fmaf(pe[2][d], w1[d], a2);
                        a3 = fmaf(pe[3][d], w1[d], a3);
                    }
                    a0 = fmaxf(a0, 0.0f); a1 = fmaxf(a1, 0.0f);
                    a2 = fmaxf(a2, 0.0f); a3 = fmaxf(a3, 0.0f);
                    const float4* w2p4 = reinterpret_cast<const float4*>(sm.W2 + (k << 4));
                    const float4 vA = w2p4[0], vB = w2p4[1], vC = w2p4[2], vD = w2p4[3];
                    const float w2[H] = { vA.x, vA.y, vA.z, vA.w, vB.x, vB.y, vB.z, vB.w,
                                          vC.x, vC.y, vC.z, vC.w, vD.x, vD.y, vD.z, vD.w };
                    #pragma unroll
                    for (int u = 0; u < H; ++u) {
                        m[0][u] = fmaf(a0, w2[u], m[0][u]);
                        m[1][u] = fmaf(a1, w2[u], m[1][u]);
                        m[2][u] = fmaf(a2, w2[u], m[2][u]);
                        m[3][u] = fmaf(a3, w2[u], m[3][u]);
                    }
                }
                // epilogue: segment accumulation over i (list i-sorted; pads keep cur_i)
                #pragma unroll
                for (int e = 0; e < 4; ++e) {
                    if (pi[e] == cur_i) {
                        #pragma unroll
                        for (int u = 0; u < H; ++u)
                            acc[u] = fmaf(pw[e], fmaxf(m[e][u] + sm.b2[u], 0.0f), acc[u]);
                    } else {
                        if (cur_i >= 0) {
                            #pragma unroll
                            for (int u = 0; u < H; ++u) atomicAdd(&sm.ctx[cur_i][u], acc[u]);
                        }
                        cur_i = pi[e];
                        #pragma unroll
                        for (int u = 0; u < H; ++u)
                            acc[u] = pw[e] * fmaxf(m[e][u] + sm.b2[u], 0.0f);
                    }
                }
            }
            if (cur_i >= 0) {
                #pragma unroll
                for (int u = 0; u < H; ++u) atomicAdd(&sm.ctx[cur_i][u], acc[u]);
            }
        }
        __syncthreads();   // B3: ctx complete

        // --- output head (one thread per agent) ---
        if (tid < NAG) {
            float hv[H], hh[H];
            #pragma unroll
            for (int u = 0; u < H; ++u) hv[u] = sm.h[tid][u] + sm.ctx[tid][u];
            const float g0 = sm.goal[tid][0], g1 = sm.goal[tid][1];
            #pragma unroll
            for (int u = 0; u < H; ++u) {
                float acc = sm.h2p1B[u];
                #pragma unroll
                for (int d = 0; d < H; ++d) acc = fmaf(hv[d], sm.h2p1W[d * 16 + u], acc);
                acc = fmaf(g0, sm.h2p1W[256 + u], fmaf(g1, sm.h2p1W[272 + u], acc));
                hh[u] = fmaxf(acc, 0.0f);
            }
            float mu0 = sm.h2p2B[0], mu1 = sm.h2p2B[1];
            #pragma unroll
            for (int d = 0; d < H; ++d) {
                mu0 = fmaf(hh[d], sm.h2p2W[d * 4 + 0], mu0);
                mu1 = fmaf(hh[d], sm.h2p2W[d * 4 + 1], mu1);
            }
            const int b = s * NAG + tid;
            out[(step * BTOT + b) * 2 + 0] = mu0;
            out[(step * BTOT + b) * 2 + 1] = mu1;
            sm.outp[tid][0] = mu0; sm.outp[tid][1] = mu1;
            sm.curr[tid][0] += mu0; sm.curr[tid][1] += mu1;
        }
        __syncthreads();   // B4: end of step
    }
}

extern "C" void kernel_launch(void* const* d_in, const int* in_sizes, int n_in,
                              void* d_out, int out_size)
{
    (void)in_sizes; (void)n_in;
    cudaFuncSetAttribute(traj_ar_kernel, cudaFuncAttributeMaxDynamicSharedMemorySize,
                         (int)sizeof(Smem));
    traj_ar_kernel<<<S_BATCH, NTHREADS, sizeof(Smem)>>>(
        (const float*)d_in[0],
        (const float*)d_in[1],
        (const float*)d_in[2],
        (const float*)d_in[4],  (const float*)d_in[5],
        (const float*)d_in[6],  (const float*)d_in[7],  (const float*)d_in[8],
        (const float*)d_in[9],  (const float*)d_in[10],
        (const float*)d_in[11], (const float*)d_in[12], (const float*)d_in[13],
        (const float*)d_in[14], (const float*)d_in[15],
        (const float*)d_in[16], (const float*)d_in[17],
        (const float*)d_in[18], (const float*)d_in[19],
        (const float*)d_in[20], (const float*)d_in[21],
        (const float*)d_in[22], (const float*)d_in[23],
        (const int*)d_in[24],
        (float*)d_out, out_size);
}

// round 14
// speedup vs baseline: 1.1775x; 1.0766x over previous
#include <cuda_runtime.h>

// TrajectoryGeneratorAR_goal: S=256 rollouts x N=64 agents, OBS=8 encoder LSTM
// steps, PRED=12 autoregressive decoder steps with pairwise pooling net.
// Round 14: the one untested (tile x warps) cell. 128 CTAs x 384 threads
// (2 samples/CTA, 3 warps/SMSP, 168-reg budget) + tile-2 pooling (4 FMA
// half-chains/thread). tile-1@3w gave -5%, tile-2@2w gave -7.7%; tile-2 is
// the largest ILP shape that can fit 168 regs without R10-style spills.

namespace {

constexpr int S_BATCH  = 256;
constexpr int NAG      = 64;     // agents per sample
constexpr int NAGC     = 128;    // agents per CTA (2 samples)
constexpr int BTOT     = S_BATCH * NAG;   // 16384
constexpr int OBS      = 8;
constexpr int PRED     = 12;
constexpr int H        = 16;
constexpr int NTHREADS = 384;
constexpr int NCTAS    = S_BATCH / 2;     // 128
constexpr int MAXPAIRS = NAGC * NAG;      // 8192

struct __align__(16) Smem {
    float h[NAGC][17];
    float c[NAGC][17];
    float ctx[NAGC][17];
    float hjp[NAGC][65];
    float curr[NAGC][2];
    float outp[NAGC][2];
    float goal[NAGC][2];
    unsigned long long nmask[NAGC];
    int   pfx[NAGC + 1];
    unsigned short plist[MAXPAIRS];   // (i<<7)|j, sorted by i
    alignas(16) float embW[32];
    alignas(16) float embB[16];
    alignas(16) float encWih[16*64];
    alignas(16) float encWhh[16*64];
    alignas(16) float encB[64];
    alignas(16) float decinW[18*16];
    alignas(16) float decinB[16];
    alignas(16) float decWih[16*64];
    alignas(16) float decWhh[16*64];
    alignas(16) float decB[64];
    alignas(16) float peW[32];
    alignas(16) float peB[16];
    alignas(16) float W1pT[64*16];   // [k][d]  (pool_W1 rows 0..15, transposed)
    alignas(16) float W1h [16*64];   // [d][k]  (pool_W1 rows 16..31)
    alignas(16) float b1  [64];
    alignas(16) float W2  [64*16];   // [k][u]
    alignas(16) float b2  [16];
    alignas(16) float h2p1W[18*16];
    alignas(16) float h2p1B[16];
    alignas(16) float h2p2W[16*4];
    alignas(16) float h2p2B[4];
};

__device__ __forceinline__ float sigm(float x)   { return 1.0f / (1.0f + __expf(-x)); }
__device__ __forceinline__ float tanh_f(float x) { return 2.0f / (1.0f + __expf(-2.0f * x)) - 1.0f; }

__device__ __forceinline__ void cpw(float* dst, const float* src, int n, int tid) {
    for (int k = tid; k < n; k += NTHREADS) dst[k] = src[k];
}

} // namespace

__global__ __launch_bounds__(NTHREADS, 1)
void traj_ar_kernel(
    const float* __restrict__ traj_rel,
    const float* __restrict__ obs_pos,
    const float* __restrict__ goal_g,
    const float* __restrict__ embW, const float* __restrict__ embB,
    const float* __restrict__ encWih, const float* __restrict__ encWhh, const float* __restrict__ encB,
    const float* __restrict__ decinW, const float* __restrict__ decinB,
    const float* __restrict__ decWih, const float* __restrict__ decWhh, const float* __restrict__ decB,
    const float* __restrict__ peW, const float* __restrict__ peB,
    const float* __restrict__ W1, const float* __restrict__ b1,
    const float* __restrict__ W2, const float* __restrict__ b2,
    const float* __restrict__ h2p1W, const float* __restrict__ h2p1B,
    const float* __restrict__ h2p2W, const float* __restrict__ h2p2B,
    const int* __restrict__ nei,
    float* __restrict__ out, int out_size)
{
    extern __shared__ unsigned char smem_raw[];
    Smem& sm = *reinterpret_cast<Smem*>(smem_raw);
    const int tid = threadIdx.x;
    const int sb  = blockIdx.x;           // CTA handles samples 2sb, 2sb+1
    const int gb  = sb * NAGC;

    if (sb == 0 && tid == 0) {
        for (int idx = PRED * BTOT * 2; idx < out_size; ++idx) out[idx] = 0.0f;
    }

    // ---------------- weight staging + state init ----------------
    cpw(sm.embW,  embW,  32,  tid);  cpw(sm.embB,  embB,  16, tid);
    cpw(sm.encWih, encWih, 1024, tid); cpw(sm.encWhh, encWhh, 1024, tid); cpw(sm.encB, encB, 64, tid);
    cpw(sm.decinW, decinW, 288, tid);  cpw(sm.decinB, decinB, 16, tid);
    cpw(sm.decWih, decWih, 1024, tid); cpw(sm.decWhh, decWhh, 1024, tid); cpw(sm.decB, decB, 64, tid);
    cpw(sm.peW, peW, 32, tid); cpw(sm.peB, peB, 16, tid);
    for (int idx = tid; idx < 1024; idx += NTHREADS) {
        const int k = idx >> 4, d = idx & 15;
        sm.W1pT[idx] = W1[d * 64 + k];
    }
    cpw(sm.W1h, W1 + 1024, 1024, tid);
    cpw(sm.b1, b1, 64, tid); cpw(sm.W2, W2, 1024, tid); cpw(sm.b2, b2, 16, tid);
    cpw(sm.h2p1W, h2p1W, 288, tid); cpw(sm.h2p1B, h2p1B, 16, tid);
    cpw(sm.h2p2W, h2p2W, 64, tid);  cpw(sm.h2p2B, h2p2B, 4, tid);

    for (int idx = tid; idx < NAGC * 17; idx += NTHREADS) {
        (&sm.h[0][0])[idx] = 0.0f; (&sm.c[0][0])[idx] = 0.0f; (&sm.ctx[0][0])[idx] = 0.0f;
    }
    if (tid < NAGC) {
        sm.nmask[tid] = 0ull;
        const int b = gb + tid;
        const float c0 = obs_pos[((OBS - 1) * BTOT + b) * 2 + 0];
        const float c1 = obs_pos[((OBS - 1) * BTOT + b) * 2 + 1];
        sm.curr[tid][0] = c0; sm.curr[tid][1] = c1;
        sm.outp[tid][0] = traj_rel[((OBS - 1) * BTOT + b) * 2 + 0];
        sm.outp[tid][1] = traj_rel[((OBS - 1) * BTOT + b) * 2 + 1];
        sm.goal[tid][0] = goal_g[b * 2 + 0] - c0;
        sm.goal[tid][1] = goal_g[b * 2 + 1] - c1;
    }
    __syncthreads();
    {   // neighbor masks for both samples: row i (0..127), local j (0..63)
        const int base = gb * NAG;
        for (int flat = tid; flat < NAGC * NAG; flat += NTHREADS) {
            if (nei[base + flat] != 0)
                atomicOr(&sm.nmask[flat >> 6], 1ull << (flat & 63));
        }
    }
    __syncthreads();
    // ---- compacted (i, j_global) pair list, sorted by i ----
    if (tid == 0) {
        int run = 0;
        for (int i = 0; i < NAGC; ++i) { sm.pfx[i] = run; run += __popcll(sm.nmask[i]); }
        sm.pfx[NAGC] = run;
    }
    __syncthreads();
    if (tid < NAGC) {
        unsigned long long m = sm.nmask[tid];
        int w = sm.pfx[tid];
        const int jbase = tid & 64;                // sample offset for j
        const unsigned short ibase = (unsigned short)(tid << 7);
        while (m) {
            const int j = __ffsll((long long)m) - 1;
            m &= m - 1;
            sm.plist[w++] = (unsigned short)(ibase | (unsigned short)(jbase + j));
        }
    }
    __syncthreads();
    const int P       = sm.pfx[NAGC];
    const int pbase   = P / NTHREADS;
    const int prem    = P - pbase * NTHREADS;
    const int mystart = tid * pbase + (tid < prem ? tid : prem);
    const int mycnt   = pbase + (tid < prem ? 1 : 0);

    // LSTM phase layout: 2 threads per agent (tid < 256), 8 gate units each
    const int a2   = tid >> 1;
    const int sub2 = tid & 1;
    const bool lstm_active = (tid < 2 * NAGC);

    // ---------------- history encoder ----------------
    if (lstm_active) {
        for (int t = 0; t < OBS; ++t) {
            const int b = gb + a2;
            const float x0 = traj_rel[(t * BTOT + b) * 2 + 0];
            const float x1 = traj_rel[(t * BTOT + b) * 2 + 1];
            float emb[H];
            #pragma unroll
            for (int u = 0; u < H; ++u)
                emb[u] = fmaxf(fmaf(x0, sm.embW[u], fmaf(x1, sm.embW[16 + u], sm.embB[u])), 0.0f);
            float hold[H];
            #pragma unroll
            for (int d = 0; d < H; ++d) hold[d] = sm.h[a2][d];
            float hn[8], cn[8];
            #pragma unroll
            for (int q = 0; q < 8; ++q) {
                const int u = sub2 * 8 + q;
                float gi = sm.encB[u], gf = sm.encB[16 + u], gg = sm.encB[32 + u], go = sm.encB[48 + u];
                #pragma unroll
                for (int d = 0; d < H; ++d) {
                    const float e = emb[d], hd = hold[d];
                    gi = fmaf(e, sm.encWih[d * 64 + u],        gi); gi = fmaf(hd, sm.encWhh[d * 64 + u],        gi);
                    gf = fmaf(e, sm.encWih[d * 64 + 16 + u],   gf); gf = fmaf(hd, sm.encWhh[d * 64 + 16 + u],   gf);
                    gg = fmaf(e, sm.encWih[d * 64 + 32 + u],   gg); gg = fmaf(hd, sm.encWhh[d * 64 + 32 + u],   gg);
                    go = fmaf(e, sm.encWih[d * 64 + 48 + u],   go); go = fmaf(hd, sm.encWhh[d * 64 + 48 + u],   go);
                }
                const float cN = sigm(gf) * sm.c[a2][u] + sigm(gi) * tanh_f(gg);
                cn[q] = cN; hn[q] = sigm(go) * tanh_f(cN);
            }
            __syncwarp();   // agent thread-pairs are intra-warp
            #pragma unroll
            for (int q = 0; q < 8; ++q) { sm.h[a2][sub2 * 8 + q] = hn[q]; sm.c[a2][sub2 * 8 + q] = cn[q]; }
            __syncwarp();
        }
        #pragma unroll
        for (int q = 0; q < 8; ++q) sm.c[a2][sub2 * 8 + q] = 0.0f;
    }
    __syncthreads();

    // ---------------- autoregressive decoder ----------------
    for (int step = 0; step < PRED; ++step) {
        // decoder input embed + LSTM (2 threads/agent, tid<256)
        if (lstm_active) {
            float ctxv[H];
            #pragma unroll
            for (int d = 0; d < H; ++d) ctxv[d] = sm.ctx[a2][d];
            const float o0 = sm.outp[a2][0], o1 = sm.outp[a2][1];
            float emb[H];
            #pragma unroll
            for (int u = 0; u < H; ++u) {
                float acc = sm.decinB[u];
                #pragma unroll
                for (int d = 0; d < H; ++d) acc = fmaf(ctxv[d], sm.decinW[d * 16 + u], acc);
                acc = fmaf(o0, sm.decinW[256 + u], fmaf(o1, sm.decinW[272 + u], acc));
                emb[u] = fmaxf(acc, 0.0f);
            }
            float hold[H];
            #pragma unroll
            for (int d = 0; d < H; ++d) hold[d] = sm.h[a2][d];
            float hn[8], cn[8];
            #pragma unroll
            for (int q = 0; q < 8; ++q) {
                const int u = sub2 * 8 + q;
                float gi = sm.decB[u], gf = sm.decB[16 + u], gg = sm.decB[32 + u], go = sm.decB[48 + u];
                #pragma unroll
                for (int d = 0; d < H; ++d) {
                    const float e = emb[d], hd = hold[d];
                    gi = fmaf(e, sm.decWih[d * 64 + u],        gi); gi = fmaf(hd, sm.decWhh[d * 64 + u],        gi);
                    gf = fmaf(e, sm.decWih[d * 64 + 16 + u],   gf); gf = fmaf(hd, sm.decWhh[d * 64 + 16 + u],   gf);
                    gg = fmaf(e, sm.decWih[d * 64 + 32 + u],   gg); gg = fmaf(hd, sm.decWhh[d * 64 + 32 + u],   gg);
                    go = fmaf(e, sm.decWih[d * 64 + 48 + u],   go); go = fmaf(hd, sm.decWhh[d * 64 + 48 + u],   go);
                }
                const float cN = sigm(gf) * sm.c[a2][u] + sigm(gi) * tanh_f(gg);
                cn[q] = cN; hn[q] = sigm(go) * tanh_f(cN);
            }
            __syncthreads();   // all reads of old h/ctx complete
            #pragma unroll
            for (int q = 0; q < 8; ++q) { sm.h[a2][sub2 * 8 + q] = hn[q]; sm.c[a2][sub2 * 8 + q] = cn[q]; }
        } else {
            __syncthreads();
        }
        __syncwarp();

        // hjp[j][k] = h_j . W1h[:,k] + b1[k]  (2 threads/agent, 32 k's each;
        // needs only the pair's own h, completed intra-warp)
        if (lstm_active) {
            const int j = a2, k0 = sub2 * 32;
            float hv[H];
            #pragma unroll
            for (int d = 0; d < H; ++d) hv[d] = sm.h[j][d];
            #pragma unroll
            for (int kk = 0; kk < 32; ++kk) {
                const int k = k0 + kk;
                float acc = sm.b1[k];
                #pragma unroll
                for (int d = 0; d < H; ++d) acc = fmaf(hv[d], sm.W1h[d * 64 + k], acc);
                sm.hjp[j][k] = acc;
            }
        }
        for (int idx = tid; idx < NAGC * 17; idx += NTHREADS) (&sm.ctx[0][0])[idx] = 0.0f;
        __syncthreads();

        // ---- pooling: tiles of 2 pairs, 4 independent FMA half-chains ----
        if (mycnt > 0) {
            int   cur_i = -1;
            float acc[H];
            for (int t = 0; t < mycnt; t += 2) {
                const int  pr0  = sm.plist[mystart + t];
                const bool has1 = (t + 1 < mycnt);
                const int  pr1  = sm.plist[mystart + (has1 ? t + 1 : t)];
                const int i0 = pr0 >> 7, j0 = pr0 & 127;
                const int i1 = pr1 >> 7, j1 = pr1 & 127;
                const float dx0 = sm.curr[i0][0] - sm.curr[j0][0];
                const float dy0 = sm.curr[i0][1] - sm.curr[j0][1];
                const float dx1 = sm.curr[i1][0] - sm.curr[j1][0];
                const float dy1 = sm.curr[i1][1] - sm.curr[j1][1];
                float pe0[H], pe1[H], m0[H], m1[H];
                #pragma unroll
                for (int u = 0; u < H; ++u) {
                    pe0[u] = fmaxf(fmaf(dx0, sm.peW[u], fmaf(dy0, sm.peW[16 + u], sm.peB[u])), 0.0f);
                    pe1[u] = fmaxf(fmaf(dx1, sm.peW[u], fmaf(dy1, sm.peW[16 + u], sm.peB[u])), 0.0f);
                    m0[u] = 0.0f; m1[u] = 0.0f;
                }
                const float* __restrict__ hj0 = sm.hjp[j0];
                const float* __restrict__ hj1 = sm.hjp[j1];
                for (int k = 0; k < 64; ++k) {
                    const float4* w1q = reinterpret_cast<const float4*>(sm.W1pT + (k << 4));
                    const float4 wa = w1q[0], wb = w1q[1], wc = w1q[2], wd = w1q[3];
                    // 4 independent half-chains (2 pairs x 2 halves)
                    float a0a = hj0[k], a0b = 0.0f;
                    float a1a = hj1[k], a1b = 0.0f;
                    a0a = fmaf(pe0[0],  wa.x, a0a); a0b = fmaf(pe0[8],  wc.x, a0b);
                    a1a = fmaf(pe1[0],  wa.x, a1a); a1b = fmaf(pe1[8],  wc.x, a1b);
                    a0a = fmaf(pe0[1],  wa.y, a0a); a0b = fmaf(pe0[9],  wc.y, a0b);
                    a1a = fmaf(pe1[1],  wa.y, a1a); a1b = fmaf(pe1[9],  wc.y, a1b);
                    a0a = fmaf(pe0[2],  wa.z, a0a); a0b = fmaf(pe0[10], wc.z, a0b);
                    a1a = fmaf(pe1[2],  wa.z, a1a); a1b = fmaf(pe1[10], wc.z, a1b);
                    a0a = fmaf(pe0[3],  wa.w, a0a); a0b = fmaf(pe0[11], wc.w, a0b);
                    a1a = fmaf(pe1[3],  wa.w, a1a); a1b = fmaf(pe1[11], wc.w, a1b);
                    a0a = fmaf(pe0[4],  wb.x, a0a); a0b = fmaf(pe0[12], wd.x, a0b);
                    a1a = fmaf(pe1[4],  wb.x, a1a); a1b = fmaf(pe1[12], wd.x, a1b);
                    a0a = fmaf(pe0[5],  wb.y, a0a); a0b = fmaf(pe0[13], wd.y, a0b);
                    a1a = fmaf(pe1[5],  wb.y, a1a); a1b = fmaf(pe1[13], wd.y, a1b);
                    a0a = fmaf(pe0[6],  wb.z, a0a); a0b = fmaf(pe0[14], wd.z, a0b);
                    a1a = fmaf(pe1[6],  wb.z, a1a); a1b = fmaf(pe1[14], wd.z, a1b);
                    a0a = fmaf(pe0[7],  wb.w, a0a); a0b = fmaf(pe0[15], wd.w, a0b);
                    a1a = fmaf(pe1[7],  wb.w, a1a); a1b = fmaf(pe1[15], wd.w, a1b);
                    const float av0 = fmaxf(a0a + a0b, 0.0f);
                    const float av1 = fmaxf(a1a + a1b, 0.0f);
                    const float4* w2q = reinterpret_cast<const float4*>(sm.W2 + (k << 4));
                    const float4 va = w2q[0], vb = w2q[1], vc = w2q[2], vd = w2q[3];
                    m0[0]  = fmaf(av0, va.x, m0[0]);  m1[0]  = fmaf(av1, va.x, m1[0]);
                    m0[1]  = fmaf(av0, va.y, m0[1]);  m1[1]  = fmaf(av1, va.y, m1[1]);
                    m0[2]  = fmaf(av0, va.z, m0[2]);  m1[2]  = fmaf(av1, va.z, m1[2]);
                    m0[3]  = fmaf(av0, va.w, m0[3]);  m1[3]  = fmaf(av1, va.w, m1[3]);
                    m0[4]  = fmaf(av0, vb.x, m0[4]);  m1[4]  = fmaf(av1, vb.x, m1[4]);
                    m0[5]  = fmaf(av0, vb.y, m0[5]);  m1[5]  = fmaf(av1, vb.y, m1[5]);
                    m0[6]  = fmaf(av0, vb.z, m0[6]);  m1[6]  = fmaf(av1, vb.z, m1[6]);
                    m0[7]  = fmaf(av0, vb.w, m0[7]);  m1[7]  = fmaf(av1, vb.w, m1[7]);
                    m0[8]  = fmaf(av0, vc.x, m0[8]);  m1[8]  = fmaf(av1, vc.x, m1[8]);
                    m0[9]  = fmaf(av0, vc.y, m0[9]);  m1[9]  = fmaf(av1, vc.y, m1[9]);
                    m0[10] = fmaf(av0, vc.z, m0[10]); m1[10] = fmaf(av1, vc.z, m1[10]);
                    m0[11] = fmaf(av0, vc.w, m0[11]); m1[11] = fmaf(av1, vc.w, m1[11]);
                    m0[12] = fmaf(av0, vd.x, m0[12]); m1[12] = fmaf(av1, vd.x, m1[12]);
                    m0[13] = fmaf(av0, vd.y, m0[13]); m1[13] = fmaf(av1, vd.y, m1[13]);
                    m0[14] = fmaf(av0, vd.z, m0[14]); m1[14] = fmaf(av1, vd.z, m1[14]);
                    m0[15] = fmaf(av0, vd.w, m0[15]); m1[15] = fmaf(av1, vd.w, m1[15]);
                }
                // epilogue pair 0
                if (i0 == cur_i) {
                    #pragma unroll
                    for (int u = 0; u < H; ++u) acc[u] += fmaxf(m0[u] + sm.b2[u], 0.0f);
                } else {
                    if (cur_i >= 0) {
                        #pragma unroll
                        for (int u = 0; u < H; ++u) atomicAdd(&sm.ctx[cur_i][u], acc[u]);
                    }
                    cur_i = i0;
                    #pragma unroll
                    for (int u = 0; u < H; ++u) acc[u] = fmaxf(m0[u] + sm.b2[u], 0.0f);
                }
                // epilogue pair 1 (skipped for the duplicated tail pad)
                if (has1) {
                    if (i1 == cur_i) {
                        #pragma unroll
                        for (int u = 0; u < H; ++u) acc[u] += fmaxf(m1[u] + sm.b2[u], 0.0f);
                    } else {
                        #pragma unroll
                        for (int u = 0; u < H; ++u) atomicAdd(&sm.ctx[cur_i][u], acc[u]);
                        cur_i = i1;
                        #pragma unroll
                        for (int u = 0; u < H; ++u) acc[u] = fmaxf(m1[u] + sm.b2[u], 0.0f);
                    }
                }
            }
            if (cur_i >= 0) {
                #pragma unroll
                for (int u = 0; u < H; ++u) atomicAdd(&sm.ctx[cur_i][u], acc[u]);
            }
        }
        __syncthreads();

        // output head (one thread per agent, both samples)
        if (tid < NAGC) {
            float hv[H], hh[H];
            #pragma unroll
            for (int u = 0; u < H; ++u) hv[u] = sm.h[tid][u] + sm.ctx[tid][u];
            const float g0 = sm.goal[tid][0], g1 = sm.goal[tid][1];
            #pragma unroll
            for (int u = 0; u < H; ++u) {
                float acc = sm.h2p1B[u];
                #pragma unroll
                for (int d = 0; d < H; ++d) acc = fmaf(hv[d], sm.h2p1W[d * 16 + u], acc);
                acc = fmaf(g0, sm.h2p1W[256 + u], fmaf(g1, sm.h2p1W[272 + u], acc));
                hh[u] = fmaxf(acc, 0.0f);
            }
            float mu0 = sm.h2p2B[0], mu1 = sm.h2p2B[1];
            #pragma unroll
            for (int d = 0; d < H; ++d) {
                mu0 = fmaf(hh[d], sm.h2p2W[d * 4 + 0], mu0);
                mu1 = fmaf(hh[d], sm.h2p2W[d * 4 + 1], mu1);
            }
            const int b = gb + tid;
            out[(step * BTOT + b) * 2 + 0] = mu0;
            out[(step * BTOT + b) * 2 + 1] = mu1;
            sm.outp[tid][0] = mu0; sm.outp[tid][1] = mu1;
            sm.curr[tid][0] += mu0; sm.curr[tid][1] += mu1;
        }
        __syncthreads();
    }
}

extern "C" void kernel_launch(void* const* d_in, const int* in_sizes, int n_in,
                              void* d_out, int out_size)
{
    (void)in_sizes; (void)n_in;
    cudaFuncSetAttribute(traj_ar_kernel, cudaFuncAttributeMaxDynamicSharedMemorySize,
                         (int)sizeof(Smem));
    traj_ar_kernel<<<NCTAS, NTHREADS, sizeof(Smem)>>>(
        (const float*)d_in[0],
        (const float*)d_in[1],
        (const float*)d_in[2],
        (const float*)d_in[4],  (const float*)d_in[5],
        (const float*)d_in[6],  (const float*)d_in[7],  (const float*)d_in[8],
        (const float*)d_in[9],  (const float*)d_in[10],
        (const float*)d_in[11], (const float*)d_in[12], (const float*)d_in[13],
        (const float*)d_in[14], (const float*)d_in[15],
        (const float*)d_in[16], (const float*)d_in[17],
        (const float*)d_in[18], (const float*)d_in[19],
        (const float*)d_in[20], (const float*)d_in[21],
        (const float*)d_in[22], (const float*)d_in[23],
        (const int*)d_in[24],
        (float*)d_out, out_size);
}

// round 15
// speedup vs baseline: 1.1874x; 1.0084x over previous
#include <cuda_runtime.h>

// TrajectoryGeneratorAR_goal: S=256 rollouts x N=64 agents, OBS=8 encoder LSTM
// steps, PRED=12 autoregressive decoder steps with pairwise pooling net.
// Round 15 = R14 winner (1440us: 128 CTAs x 384 thr, 2 samples/CTA,
// 3 warps/SMSP, 168 regs, tile-2 pooling) with the pooling tile widened to 3
// (6 independent FMA half-chains, 2.7 LDS/pair/k) — the untested interior
// point of the register budget. Everything else byte-identical to R14.

namespace {

constexpr int S_BATCH  = 256;
constexpr int NAG      = 64;     // agents per sample
constexpr int NAGC     = 128;    // agents per CTA (2 samples)
constexpr int BTOT     = S_BATCH * NAG;   // 16384
constexpr int OBS      = 8;
constexpr int PRED     = 12;
constexpr int H        = 16;
constexpr int NTHREADS = 384;
constexpr int NCTAS    = S_BATCH / 2;     // 128
constexpr int MAXPAIRS = NAGC * NAG;      // 8192

struct __align__(16) Smem {
    float h[NAGC][17];
    float c[NAGC][17];
    float ctx[NAGC][17];
    float hjp[NAGC][65];
    float curr[NAGC][2];
    float outp[NAGC][2];
    float goal[NAGC][2];
    unsigned long long nmask[NAGC];
    int   pfx[NAGC + 1];
    unsigned short plist[MAXPAIRS];   // (i<<7)|j, sorted by i
    alignas(16) float embW[32];
    alignas(16) float embB[16];
    alignas(16) float encWih[16*64];
    alignas(16) float encWhh[16*64];
    alignas(16) float encB[64];
    alignas(16) float decinW[18*16];
    alignas(16) float decinB[16];
    alignas(16) float decWih[16*64];
    alignas(16) float decWhh[16*64];
    alignas(16) float decB[64];
    alignas(16) float peW[32];
    alignas(16) float peB[16];
    alignas(16) float W1pT[64*16];   // [k][d]  (pool_W1 rows 0..15, transposed)
    alignas(16) float W1h [16*64];   // [d][k]  (pool_W1 rows 16..31)
    alignas(16) float b1  [64];
    alignas(16) float W2  [64*16];   // [k][u]
    alignas(16) float b2  [16];
    alignas(16) float h2p1W[18*16];
    alignas(16) float h2p1B[16];
    alignas(16) float h2p2W[16*4];
    alignas(16) float h2p2B[4];
};

__device__ __forceinline__ float sigm(float x)   { return 1.0f / (1.0f + __expf(-x)); }
__device__ __forceinline__ float tanh_f(float x) { return 2.0f / (1.0f + __expf(-2.0f * x)) - 1.0f; }

__device__ __forceinline__ void cpw(float* dst, const float* src, int n, int tid) {
    for (int k = tid; k < n; k += NTHREADS) dst[k] = src[k];
}

} // namespace

__global__ __launch_bounds__(NTHREADS, 1)
void traj_ar_kernel(
    const float* __restrict__ traj_rel,
    const float* __restrict__ obs_pos,
    const float* __restrict__ goal_g,
    const float* __restrict__ embW, const float* __restrict__ embB,
    const float* __restrict__ encWih, const float* __restrict__ encWhh, const float* __restrict__ encB,
    const float* __restrict__ decinW, const float* __restrict__ decinB,
    const float* __restrict__ decWih, const float* __restrict__ decWhh, const float* __restrict__ decB,
    const float* __restrict__ peW, const float* __restrict__ peB,
    const float* __restrict__ W1, const float* __restrict__ b1,
    const float* __restrict__ W2, const float* __restrict__ b2,
    const float* __restrict__ h2p1W, const float* __restrict__ h2p1B,
    const float* __restrict__ h2p2W, const float* __restrict__ h2p2B,
    const int* __restrict__ nei,
    float* __restrict__ out, int out_size)
{
    extern __shared__ unsigned char smem_raw[];
    Smem& sm = *reinterpret_cast<Smem*>(smem_raw);
    const int tid = threadIdx.x;
    const int sb  = blockIdx.x;           // CTA handles samples 2sb, 2sb+1
    const int gb  = sb * NAGC;

    if (sb == 0 && tid == 0) {
        for (int idx = PRED * BTOT * 2; idx < out_size; ++idx) out[idx] = 0.0f;
    }

    // ---------------- weight staging + state init ----------------
    cpw(sm.embW,  embW,  32,  tid);  cpw(sm.embB,  embB,  16, tid);
    cpw(sm.encWih, encWih, 1024, tid); cpw(sm.encWhh, encWhh, 1024, tid); cpw(sm.encB, encB, 64, tid);
    cpw(sm.decinW, decinW, 288, tid);  cpw(sm.decinB, decinB, 16, tid);
    cpw(sm.decWih, decWih, 1024, tid); cpw(sm.decWhh, decWhh, 1024, tid); cpw(sm.decB, decB, 64, tid);
    cpw(sm.peW, peW, 32, tid); cpw(sm.peB, peB, 16, tid);
    for (int idx = tid; idx < 1024; idx += NTHREADS) {
        const int k = idx >> 4, d = idx & 15;
        sm.W1pT[idx] = W1[d * 64 + k];
    }
    cpw(sm.W1h, W1 + 1024, 1024, tid);
    cpw(sm.b1, b1, 64, tid); cpw(sm.W2, W2, 1024, tid); cpw(sm.b2, b2, 16, tid);
    cpw(sm.h2p1W, h2p1W, 288, tid); cpw(sm.h2p1B, h2p1B, 16, tid);
    cpw(sm.h2p2W, h2p2W, 64, tid);  cpw(sm.h2p2B, h2p2B, 4, tid);

    for (int idx = tid; idx < NAGC * 17; idx += NTHREADS) {
        (&sm.h[0][0])[idx] = 0.0f; (&sm.c[0][0])[idx] = 0.0f; (&sm.ctx[0][0])[idx] = 0.0f;
    }
    if (tid < NAGC) {
        sm.nmask[tid] = 0ull;
        const int b = gb + tid;
        const float c0 = obs_pos[((OBS - 1) * BTOT + b) * 2 + 0];
        const float c1 = obs_pos[((OBS - 1) * BTOT + b) * 2 + 1];
        sm.curr[tid][0] = c0; sm.curr[tid][1] = c1;
        sm.outp[tid][0] = traj_rel[((OBS - 1) * BTOT + b) * 2 + 0];
        sm.outp[tid][1] = traj_rel[((OBS - 1) * BTOT + b) * 2 + 1];
        sm.goal[tid][0] = goal_g[b * 2 + 0] - c0;
        sm.goal[tid][1] = goal_g[b * 2 + 1] - c1;
    }
    __syncthreads();
    {   // neighbor masks for both samples: row i (0..127), local j (0..63)
        const int base = gb * NAG;
        for (int flat = tid; flat < NAGC * NAG; flat += NTHREADS) {
            if (nei[base + flat] != 0)
                atomicOr(&sm.nmask[flat >> 6], 1ull << (flat & 63));
        }
    }
    __syncthreads();
    // ---- compacted (i, j_global) pair list, sorted by i ----
    if (tid == 0) {
        int run = 0;
        for (int i = 0; i < NAGC; ++i) { sm.pfx[i] = run; run += __popcll(sm.nmask[i]); }
        sm.pfx[NAGC] = run;
    }
    __syncthreads();
    if (tid < NAGC) {
        unsigned long long m = sm.nmask[tid];
        int w = sm.pfx[tid];
        const int jbase = tid & 64;                // sample offset for j
        const unsigned short ibase = (unsigned short)(tid << 7);
        while (m) {
            const int j = __ffsll((long long)m) - 1;
            m &= m - 1;
            sm.plist[w++] = (unsigned short)(ibase | (unsigned short)(jbase + j));
        }
    }
    __syncthreads();
    const int P       = sm.pfx[NAGC];
    const int pbase   = P / NTHREADS;
    const int prem    = P - pbase * NTHREADS;
    const int mystart = tid * pbase + (tid < prem ? tid : prem);
    const int mycnt   = pbase + (tid < prem ? 1 : 0);

    // LSTM phase layout: 2 threads per agent (tid < 256), 8 gate units each
    const int a2   = tid >> 1;
    const int sub2 = tid & 1;
    const bool lstm_active = (tid < 2 * NAGC);

    // ---------------- history encoder ----------------
    if (lstm_active) {
        for (int t = 0; t < OBS; ++t) {
            const int b = gb + a2;
            const float x0 = traj_rel[(t * BTOT + b) * 2 + 0];
            const float x1 = traj_rel[(t * BTOT + b) * 2 + 1];
            float emb[H];
            #pragma unroll
            for (int u = 0; u < H; ++u)
                emb[u] = fmaxf(fmaf(x0, sm.embW[u], fmaf(x1, sm.embW[16 + u], sm.embB[u])), 0.0f);
            float hold[H];
            #pragma unroll
            for (int d = 0; d < H; ++d) hold[d] = sm.h[a2][d];
            float hn[8], cn[8];
            #pragma unroll
            for (int q = 0; q < 8; ++q) {
                const int u = sub2 * 8 + q;
                float gi = sm.encB[u], gf = sm.encB[16 + u], gg = sm.encB[32 + u], go = sm.encB[48 + u];
                #pragma unroll
                for (int d = 0; d < H; ++d) {
                    const float e = emb[d], hd = hold[d];
                    gi = fmaf(e, sm.encWih[d * 64 + u],        gi); gi = fmaf(hd, sm.encWhh[d * 64 + u],        gi);
                    gf = fmaf(e, sm.encWih[d * 64 + 16 + u],   gf); gf = fmaf(hd, sm.encWhh[d * 64 + 16 + u],   gf);
                    gg = fmaf(e, sm.encWih[d * 64 + 32 + u],   gg); gg = fmaf(hd, sm.encWhh[d * 64 + 32 + u],   gg);
                    go = fmaf(e, sm.encWih[d * 64 + 48 + u],   go); go = fmaf(hd, sm.encWhh[d * 64 + 48 + u],   go);
                }
                const float cN = sigm(gf) * sm.c[a2][u] + sigm(gi) * tanh_f(gg);
                cn[q] = cN; hn[q] = sigm(go) * tanh_f(cN);
            }
            __syncwarp();   // agent thread-pairs are intra-warp
            #pragma unroll
            for (int q = 0; q < 8; ++q) { sm.h[a2][sub2 * 8 + q] = hn[q]; sm.c[a2][sub2 * 8 + q] = cn[q]; }
            __syncwarp();
        }
        #pragma unroll
        for (int q = 0; q < 8; ++q) sm.c[a2][sub2 * 8 + q] = 0.0f;
    }
    __syncthreads();

    // ---------------- autoregressive decoder ----------------
    for (int step = 0; step < PRED; ++step) {
        // decoder input embed + LSTM (2 threads/agent, tid<256)
        if (lstm_active) {
            float ctxv[H];
            #pragma unroll
            for (int d = 0; d < H; ++d) ctxv[d] = sm.ctx[a2][d];
            const float o0 = sm.outp[a2][0], o1 = sm.outp[a2][1];
            float emb[H];
            #pragma unroll
            for (int u = 0; u < H; ++u) {
                float acc = sm.decinB[u];
                #pragma unroll
                for (int d = 0; d < H; ++d) acc = fmaf(ctxv[d], sm.decinW[d * 16 + u], acc);
                acc = fmaf(o0, sm.decinW[256 + u], fmaf(o1, sm.decinW[272 + u], acc));
                emb[u] = fmaxf(acc, 0.0f);
            }
            float hold[H];
            #pragma unroll
            for (int d = 0; d < H; ++d) hold[d] = sm.h[a2][d];
            float hn[8], cn[8];
            #pragma unroll
            for (int q = 0; q < 8; ++q) {
                const int u = sub2 * 8 + q;
                float gi = sm.decB[u], gf = sm.decB[16 + u], gg = sm.decB[32 + u], go = sm.decB[48 + u];
                #pragma unroll
                for (int d = 0; d < H; ++d) {
                    const float e = emb[d], hd = hold[d];
                    gi = fmaf(e, sm.decWih[d * 64 + u],        gi); gi = fmaf(hd, sm.decWhh[d * 64 + u],        gi);
                    gf = fmaf(e, sm.decWih[d * 64 + 16 + u],   gf); gf = fmaf(hd, sm.decWhh[d * 64 + 16 + u],   gf);
                    gg = fmaf(e, sm.decWih[d * 64 + 32 + u],   gg); gg = fmaf(hd, sm.decWhh[d * 64 + 32 + u],   gg);
                    go = fmaf(e, sm.decWih[d * 64 + 48 + u],   go); go = fmaf(hd, sm.decWhh[d * 64 + 48 + u],   go);
                }
                const float cN = sigm(gf) * sm.c[a2][u] + sigm(gi) * tanh_f(gg);
                cn[q] = cN; hn[q] = sigm(go) * tanh_f(cN);
            }
            __syncthreads();   // all reads of old h/ctx complete
            #pragma unroll
            for (int q = 0; q < 8; ++q) { sm.h[a2][sub2 * 8 + q] = hn[q]; sm.c[a2][sub2 * 8 + q] = cn[q]; }
        } else {
            __syncthreads();
        }
        __syncwarp();

        // hjp[j][k] = h_j . W1h[:,k] + b1[k]  (2 threads/agent, 32 k's each;
        // needs only the pair's own h, completed intra-warp)
        if (lstm_active) {
            const int j = a2, k0 = sub2 * 32;
            float hv[H];
            #pragma unroll
            for (int d = 0; d < H; ++d) hv[d] = sm.h[j][d];
            #pragma unroll
            for (int kk = 0; kk < 32; ++kk) {
                const int k = k0 + kk;
                float acc = sm.b1[k];
                #pragma unroll
                for (int d = 0; d < H; ++d) acc = fmaf(hv[d], sm.W1h[d * 64 + k], acc);
                sm.hjp[j][k] = acc;
            }
        }
        for (int idx = tid; idx < NAGC * 17; idx += NTHREADS) (&sm.ctx[0][0])[idx] = 0.0f;
        __syncthreads();

        // ---- pooling: tiles of 3 pairs (clamped zero-weight pads),
        //      6 independent FMA half-chains per k ----
        if (mycnt > 0) {
            int   cur_i = -1;
            float acc[H];
            for (int t = 0; t < mycnt; t += 3) {
                int pi[3], pj[3];
                float pw[3];
                #pragma unroll
                for (int e = 0; e < 3; ++e) {
                    const int tt  = t + e;
                    const int idx = mystart + (tt < mycnt ? tt : mycnt - 1);
                    const int pr  = sm.plist[idx];
                    pi[e] = pr >> 7; pj[e] = pr & 127;
                    pw[e] = (tt < mycnt) ? 1.0f : 0.0f;
                }
                float pe[3][H], m[3][H];
                #pragma unroll
                for (int e = 0; e < 3; ++e) {
                    const float dx = sm.curr[pi[e]][0] - sm.curr[pj[e]][0];
                    const float dy = sm.curr[pi[e]][1] - sm.curr[pj[e]][1];
                    #pragma unroll
                    for (int u = 0; u < H; ++u) {
                        pe[e][u] = fmaxf(fmaf(dx, sm.peW[u], fmaf(dy, sm.peW[16 + u], sm.peB[u])), 0.0f);
                        m[e][u]  = 0.0f;
                    }
                }
                const float* __restrict__ hj0 = sm.hjp[pj[0]];
                const float* __restrict__ hj1 = sm.hjp[pj[1]];
                const float* __restrict__ hj2 = sm.hjp[pj[2]];
                for (int k = 0; k < 64; ++k) {
                    const float4* w1q = reinterpret_cast<const float4*>(sm.W1pT + (k << 4));
                    const float4 wa = w1q[0], wb = w1q[1], wc = w1q[2], wd = w1q[3];
                    // 6 independent half-chains (3 pairs x 2 halves)
                    float a0a = hj0[k], a0b = 0.0f;
                    float a1a = hj1[k], a1b = 0.0f;
                    float a2a = hj2[k], a2b = 0.0f;
                    a0a = fmaf(pe[0][0],  wa.x, a0a); a0b = fmaf(pe[0][8],  wc.x, a0b);
                    a1a = fmaf(pe[1][0],  wa.x, a1a); a1b = fmaf(pe[1][8],  wc.x, a1b);
                    a2a = fmaf(pe[2][0],  wa.x, a2a); a2b = fmaf(pe[2][8],  wc.x, a2b);
                    a0a = fmaf(pe[0][1],  wa.y, a0a); a0b = fmaf(pe[0][9],  wc.y, a0b);
                    a1a = fmaf(pe[1][1],  wa.y, a1a); a1b = fmaf(pe[1][9],  wc.y, a1b);
                    a2a = fmaf(pe[2][1],  wa.y, a2a); a2b = fmaf(pe[2][9],  wc.y, a2b);
                    a0a = fmaf(pe[0][2],  wa.z, a0a); a0b = fmaf(pe[0][10], wc.z, a0b);
                    a1a = fmaf(pe[1][2],  wa.z, a1a); a1b = fmaf(pe[1][10], wc.z, a1b);
                    a2a = fmaf(pe[2][2],  wa.z, a2a); a2b = fmaf(pe[2][10], wc.z, a2b);
                    a0a = fmaf(pe[0][3],  wa.w, a0a); a0b = fmaf(pe[0][11], wc.w, a0b);
                    a1a = fmaf(pe[1][3],  wa.w, a1a); a1b = fmaf(pe[1][11], wc.w, a1b);
                    a2a = fmaf(pe[2][3],  wa.w, a2a); a2b = fmaf(pe[2][11], wc.w, a2b);
                    a0a = fmaf(pe[0][4],  wb.x, a0a); a0b = fmaf(pe[0][12], wd.x, a0b);
                    a1a = fmaf(pe[1][4],  wb.x, a1a); a1b = fmaf(pe[1][12], wd.x, a1b);
                    a2a = fmaf(pe[2][4],  wb.x, a2a); a2b = fmaf(pe[2][12], wd.x, a2b);
                    a0a = fmaf(pe[0][5],  wb.y, a0a); a0b = fmaf(pe[0][13], wd.y, a0b);
                    a1a = fmaf(pe[1][5],  wb.y, a1a); a1b = fmaf(pe[1][13], wd.y, a1b);
                    a2a = fmaf(pe[2][5],  wb.y, a2a); a2b = fmaf(pe[2][13], wd.y, a2b);
                    a0a = fmaf(pe[0][6],  wb.z, a0a); a0b = fmaf(pe[0][14], wd.z, a0b);
                    a1a = fmaf(pe[1][6],  wb.z, a1a); a1b = fmaf(pe[1][14], wd.z, a1b);
                    a2a = fmaf(pe[2][6],  wb.z, a2a); a2b = fmaf(pe[2][14], wd.z, a2b);
                    a0a = fmaf(pe[0][7],  wb.w, a0a); a0b = fmaf(pe[0][15], wd.w, a0b);
                    a1a = fmaf(pe[1][7],  wb.w, a1a); a1b = fmaf(pe[1][15], wd.w, a1b);
                    a2a = fmaf(pe[2][7],  wb.w, a2a); a2b = fmaf(pe[2][15], wd.w, a2b);
                    const float av0 = fmaxf(a0a + a0b, 0.0f);
                    const float av1 = fmaxf(a1a + a1b, 0.0f);
                    const float av2 = fmaxf(a2a + a2b, 0.0f);
                    const float4* w2q = reinterpret_cast<const float4*>(sm.W2 + (k << 4));
                    const float4 va = w2q[0], vb = w2q[1], vc = w2q[2], vd = w2q[3];
                    m[0][0]  = fmaf(av0, va.x, m[0][0]);  m[1][0]  = fmaf(av1, va.x, m[1][0]);  m[2][0]  = fmaf(av2, va.x, m[2][0]);
                    m[0][1]  = fmaf(av0, va.y, m[0][1]);  m[1][1]  = fmaf(av1, va.y, m[1][1]);  m[2][1]  = fmaf(av2, va.y, m[2][1]);
                    m[0][2]  = fmaf(av0, va.z, m[0][2]);  m[1][2]  = fmaf(av1, va.z, m[1][2]);  m[2][2]  = fmaf(av2, va.z, m[2][2]);
                    m[0][3]  = fmaf(av0, va.w, m[0][3]);  m[1][3]  = fmaf(av1, va.w, m[1][3]);  m[2][3]  = fmaf(av2, va.w, m[2][3]);
                    m[0][4]  = fmaf(av0, vb.x, m[0][4]);  m[1][4]  = fmaf(av1, vb.x, m[1][4]);  m[2][4]  = fmaf(av2, vb.x, m[2][4]);
                    m[0][5]  = fmaf(av0, vb.y, m[0][5]);  m[1][5]  = fmaf(av1, vb.y, m[1][5]);  m[2][5]  = fmaf(av2, vb.y, m[2][5]);
                    m[0][6]  = fmaf(av0, vb.z, m[0][6]);  m[1][6]  = fmaf(av1, vb.z, m[1][6]);  m[2][6]  = fmaf(av2, vb.z, m[2][6]);
                    m[0][7]  = fmaf(av0, vb.w, m[0][7]);  m[1][7]  = fmaf(av1, vb.w, m[1][7]);  m[2][7]  = fmaf(av2, vb.w, m[2][7]);
                    m[0][8]  = fmaf(av0, vc.x, m[0][8]);  m[1][8]  = fmaf(av1, vc.x, m[1][8]);  m[2][8]  = fmaf(av2, vc.x, m[2][8]);
                    m[0][9]  = fmaf(av0, vc.y, m[0][9]);  m[1][9]  = fmaf(av1, vc.y, m[1][9]);  m[2][9]  = fmaf(av2, vc.y, m[2][9]);
                    m[0][10] = fmaf(av0, vc.z, m[0][10]); m[1][10] = fmaf(av1, vc.z, m[1][10]); m[2][10] = fmaf(av2, vc.z, m[2][10]);
                    m[0][11] = fmaf(av0, vc.w, m[0][11]); m[1][11] = fmaf(av1, vc.w, m[1][11]); m[2][11] = fmaf(av2, vc.w, m[2][11]);
                    m[0][12] = fmaf(av0, vd.x, m[0][12]); m[1][12] = fmaf(av1, vd.x, m[1][12]); m[2][12] = fmaf(av2, vd.x, m[2][12]);
                    m[0][13] = fmaf(av0, vd.y, m[0][13]); m[1][13] = fmaf(av1, vd.y, m[1][13]); m[2][13] = fmaf(av2, vd.y, m[2][13]);
                    m[0][14] = fmaf(av0, vd.z, m[0][14]); m[1][14] = fmaf(av1, vd.z, m[1][14]); m[2][14] = fmaf(av2, vd.z, m[2][14]);
                    m[0][15] = fmaf(av0, vd.w, m[0][15]); m[1][15] = fmaf(av1, vd.w, m[1][15]); m[2][15] = fmaf(av2, vd.w, m[2][15]);
                }
                // epilogue: segment accumulation over i (list i-sorted; pads
                // duplicate the last real pair's i so they never open a segment)
                #pragma unroll
                for (int e = 0; e < 3; ++e) {
                    if (pi[e] == cur_i) {
                        #pragma unroll
                        for (int u = 0; u < H; ++u)
                            acc[u] = fmaf(pw[e], fmaxf(m[e][u] + sm.b2[u], 0.0f), acc[u]);
                    } else {
                        if (cur_i >= 0) {
                            #pragma unroll
                            for (int u = 0; u < H; ++u) atomicAdd(&sm.ctx[cur_i][u], acc[u]);
                        }
                        cur_i = pi[e];
                        #pragma unroll
                        for (int u = 0; u < H; ++u)
                            acc[u] = pw[e] * fmaxf(m[e][u] + sm.b2[u], 0.0f);
                    }
                }
            }
            if (cur_i >= 0) {
                #pragma unroll
                for (int u = 0; u < H; ++u) atomicAdd(&sm.ctx[cur_i][u], acc[u]);
            }
        }
        __syncthreads();

        // output head (one thread per agent, both samples)
        if (tid < NAGC) {
            float hv[H], hh[H];
            #pragma unroll
            for (int u = 0; u < H; ++u) hv[u] = sm.h[tid][u] + sm.ctx[tid][u];
            const float g0 = sm.goal[tid][0], g1 = sm.goal[tid][1];
            #pragma unroll
            for (int u = 0; u < H; ++u) {
                float acc = sm.h2p1B[u];
                #pragma unroll
                for (int d = 0; d < H; ++d) acc = fmaf(hv[d], sm.h2p1W[d * 16 + u], acc);
                acc = fmaf(g0, sm.h2p1W[256 + u], fmaf(g1, sm.h2p1W[272 + u], acc));
                hh[u] = fmaxf(acc, 0.0f);
            }
            float mu0 = sm.h2p2B[0], mu1 = sm.h2p2B[1];
            #pragma unroll
            for (int d = 0; d < H; ++d) {
                mu0 = fmaf(hh[d], sm.h2p2W[d * 4 + 0], mu0);
                mu1 = fmaf(hh[d], sm.h2p2W[d * 4 + 1], mu1);
            }
            const int b = gb + tid;
            out[(step * BTOT + b) * 2 + 0] = mu0;
            out[(step * BTOT + b) * 2 + 1] = mu1;
            sm.outp[tid][0] = mu0; sm.outp[tid][1] = mu1;
            sm.curr[tid][0] += mu0; sm.curr[tid][1] += mu1;
        }
        __syncthreads();
    }
}

extern "C" void kernel_launch(void* const* d_in, const int* in_sizes, int n_in,
                              void* d_out, int out_size)
{
    (void)in_sizes; (void)n_in;
    cudaFuncSetAttribute(traj_ar_kernel, cudaFuncAttributeMaxDynamicSharedMemorySize,
                         (int)sizeof(Smem));
    traj_ar_kernel<<<NCTAS, NTHREADS, sizeof(Smem)>>>(
        (const float*)d_in[0],
        (const float*)d_in[1],
        (const float*)d_in[2],
        (const float*)d_in[4],  (const float*)d_in[5],
        (const float*)d_in[6],  (const float*)d_in[7],  (const float*)d_in[8],
        (const float*)d_in[9],  (const float*)d_in[10],
        (const float*)d_in[11], (const float*)d_in[12], (const float*)d_in[13],
        (const float*)d_in[14], (const float*)d_in[15],
        (const float*)d_in[16], (const float*)d_in[17],
        (const float*)d_in[18], (const float*)d_in[19],
        (const float*)d_in[20], (const float*)d_in[21],
        (const float*)d_in[22], (const float*)d_in[23],
        (const int*)d_in[24],
        (float*)d_out, out_size);
}